// round 10
// baseline (speedup 1.0000x reference)
#include <cuda_runtime.h>
#include <cuda_bf16.h>
#include <math.h>
#include <stdint.h>

// Problem dims
#define TB   2
#define TT   2048
#define TD   1024
#define TH   16
#define THD  64
#define TDFF 4096
#define BT   (TB*TT)

// ------------------------- scratch (device globals) ------------------------
__device__ __nv_bfloat16 g_hA  [(size_t)BT * 2 * TD];     // LN out, split
__device__ __nv_bfloat16 g_qkvb[(size_t)BT * 6 * TD];     // qkv split: hi 3TD | lo 3TD
__device__ __nv_bfloat16 g_oA  [(size_t)BT * 2 * TD];     // attn out, split
__device__ float         g_x2  [(size_t)BT * TD];
__device__ __nv_bfloat16 g_ffA [(size_t)BT * 2 * TDFF];
// B-operands (weights), K-major [N][2K]: (hi | lo)
__device__ __nv_bfloat16 g_wqkv[(size_t)(3*TD) * (2*TD)];
__device__ __nv_bfloat16 g_wo  [(size_t)TD * (2*TD)];
__device__ __nv_bfloat16 g_w1  [(size_t)TDFF * (2*TD)];
__device__ __nv_bfloat16 g_w2  [(size_t)TD * (2*TDFF)];

__device__ __forceinline__ uint32_t smem_u32(const void* p) {
    uint32_t a;
    asm("{ .reg .u64 t; cvta.to.shared.u64 t, %1; cvt.u32.u64 %0, t; }"
        : "=r"(a) : "l"(p));
    return a;
}
__device__ __forceinline__ void bf16split(float v, __nv_bfloat16& hi,
                                          __nv_bfloat16& lo) {
    hi = __float2bfloat16(v);
    lo = __float2bfloat16(v - __bfloat162float(hi));
}
__device__ __forceinline__ uint32_t packbf2(float x, float y) {
    __nv_bfloat162 t = __floats2bfloat162_rn(x, y);
    return *(uint32_t*)&t;
}
__device__ __forceinline__ void cp16(uint32_t sdst, const void* gsrc) {
    asm volatile("cp.async.cg.shared.global [%0], [%1], 16;"
                 :: "r"(sdst), "l"(gsrc));
}
__device__ __forceinline__ void ldm4(uint32_t addr, uint32_t& r0, uint32_t& r1,
                                     uint32_t& r2, uint32_t& r3) {
    asm volatile("ldmatrix.sync.aligned.m8n8.x4.shared.b16 {%0,%1,%2,%3}, [%4];"
                 : "=r"(r0), "=r"(r1), "=r"(r2), "=r"(r3) : "r"(addr));
}
__device__ __forceinline__ void ldm4t(uint32_t addr, uint32_t& r0, uint32_t& r1,
                                      uint32_t& r2, uint32_t& r3) {
    asm volatile("ldmatrix.sync.aligned.m8n8.x4.trans.shared.b16 {%0,%1,%2,%3}, [%4];"
                 : "=r"(r0), "=r"(r1), "=r"(r2), "=r"(r3) : "r"(addr));
}
__device__ __forceinline__ void mma16816(float* d, const uint32_t* a,
                                         uint32_t b0, uint32_t b1) {
    asm volatile(
        "mma.sync.aligned.m16n8k16.row.col.f32.bf16.bf16.f32 "
        "{%0,%1,%2,%3}, {%4,%5,%6,%7}, {%8,%9}, {%0,%1,%2,%3};"
        : "+f"(d[0]), "+f"(d[1]), "+f"(d[2]), "+f"(d[3])
        : "r"(a[0]), "r"(a[1]), "r"(a[2]), "r"(a[3]), "r"(b0), "r"(b1));
}

// ------------------------- weight convert (tiled transpose + split) --------
__global__ void __launch_bounds__(256) wconv_kernel(
    const float* __restrict__ src, int srcld,
    __nv_bfloat16* __restrict__ dst, int dstld, int khalf) {
    __shared__ float t[32][33];
    int k0 = blockIdx.y * 32, n0 = blockIdx.x * 32;
    int tx = threadIdx.x, ty = threadIdx.y;
    #pragma unroll
    for (int i = 0; i < 4; i++)
        t[ty + 8 * i][tx] = src[(size_t)(k0 + ty + 8 * i) * srcld + n0 + tx];
    __syncthreads();
    #pragma unroll
    for (int i = 0; i < 4; i++) {
        int n = n0 + ty + 8 * i, k = k0 + tx;
        __nv_bfloat16 hi, lo;
        bf16split(t[tx][ty + 8 * i], hi, lo);
        dst[(size_t)n * dstld + k] = hi;
        dst[(size_t)n * dstld + khalf + k] = lo;
    }
}

__global__ void __launch_bounds__(256) qkvconv_kernel(
    const float* __restrict__ Wq, const float* __restrict__ Wk,
    const float* __restrict__ Wv, __nv_bfloat16* __restrict__ dst) {
    __shared__ float t[32][33];
    int z = blockIdx.z;
    int third = z >> 4, h = z & 15;
    const float* W = (third == 0) ? Wq : ((third == 1) ? Wk : Wv);
    const float* src = W + (size_t)h * TD * THD;
    int k0 = blockIdx.y * 32, n0 = blockIdx.x * 32;
    int tx = threadIdx.x, ty = threadIdx.y;
    #pragma unroll
    for (int i = 0; i < 4; i++)
        t[ty + 8 * i][tx] = src[(size_t)(k0 + ty + 8 * i) * THD + n0 + tx];
    __syncthreads();
    #pragma unroll
    for (int i = 0; i < 4; i++) {
        int nl = n0 + ty + 8 * i, k = k0 + tx;
        int n = third * TD + h * THD + nl;
        __nv_bfloat16 hi, lo;
        bf16split(t[tx][ty + 8 * i], hi, lo);
        dst[(size_t)n * (2 * TD) + k] = hi;
        dst[(size_t)n * (2 * TD) + TD + k] = lo;
    }
}

// ------------------------- LayerNorm -> split bf16 A operand ---------------
__global__ void __launch_bounds__(256) ln_kernel(const float* __restrict__ x,
                                                 const float* __restrict__ g,
                                                 const float* __restrict__ b,
                                                 __nv_bfloat16* __restrict__ outA) {
    __shared__ float sh[16];
    int row = blockIdx.x;
    int tid = threadIdx.x;
    const float* xr = x + (size_t)row * TD;
    float4 v = *(const float4*)(xr + tid * 4);
    float s  = v.x + v.y + v.z + v.w;
    float sq = v.x * v.x + v.y * v.y + v.z * v.z + v.w * v.w;
    #pragma unroll
    for (int o = 16; o; o >>= 1) {
        s  += __shfl_xor_sync(0xffffffffu, s, o);
        sq += __shfl_xor_sync(0xffffffffu, sq, o);
    }
    if ((tid & 31) == 0) { sh[tid >> 5] = s; sh[(tid >> 5) + 8] = sq; }
    __syncthreads();
    if (tid < 32) {
        float a = (tid < 8) ? sh[tid] : 0.0f;
        float c = (tid < 8) ? sh[tid + 8] : 0.0f;
        #pragma unroll
        for (int o = 4; o; o >>= 1) {
            a += __shfl_xor_sync(0xffffffffu, a, o);
            c += __shfl_xor_sync(0xffffffffu, c, o);
        }
        if (tid == 0) { sh[0] = a; sh[1] = c; }
    }
    __syncthreads();
    float mu  = sh[0] * (1.0f / TD);
    float var = sh[1] * (1.0f / TD) - mu * mu;
    float rs  = rsqrtf(var + 1e-5f);
    float4 gg = *(const float4*)(g + tid * 4);
    float4 bb = *(const float4*)(b + tid * 4);
    float o0 = (v.x - mu) * rs * gg.x + bb.x;
    float o1 = (v.y - mu) * rs * gg.y + bb.y;
    float o2 = (v.z - mu) * rs * gg.z + bb.z;
    float o3 = (v.w - mu) * rs * gg.w + bb.w;
    __nv_bfloat16 h0, l0, h1, l1, h2, l2, h3, l3;
    bf16split(o0, h0, l0); bf16split(o1, h1, l1);
    bf16split(o2, h2, l2); bf16split(o3, h3, l3);
    __nv_bfloat16* base = outA + (size_t)row * (2 * TD) + tid * 4;
    *(__nv_bfloat162*)(base + 0) = __halves2bfloat162(h0, h1);
    *(__nv_bfloat162*)(base + 2) = __halves2bfloat162(h2, h3);
    *(__nv_bfloat162*)(base + TD + 0) = __halves2bfloat162(l0, l1);
    *(__nv_bfloat162*)(base + TD + 2) = __halves2bfloat162(l2, l3);
}

// ------------------------- HMMA split-bf16 GEMM ----------------------------
// 3-stage cp.async ring, ONE __syncthreads per 64-k stage.
// EPI: 0 fp32; 1 +bias+res fp32; 2 +bias GELU split-bf16; 3 plain split-bf16
#define MSTRIDE 72
#define STG     (128 * MSTRIDE * 2)     // 18432 B per operand stage
#define MDYN    (6 * STG)               // 3 stages x (A+B) = 110592 B

template <int EPI>
__global__ void __launch_bounds__(256) mgemm_kernel(
    const __nv_bfloat16* __restrict__ A, const __nv_bfloat16* __restrict__ B,
    float* __restrict__ Cf, __nv_bfloat16* __restrict__ Cb,
    int K, int ldA, int ldB, int ldc, int khalf,
    const float* __restrict__ bias, const float* __restrict__ res, int ldres) {
    extern __shared__ char smp[];
    uint32_t smb = smem_u32(smp);
    int tid = threadIdx.x, wid = tid >> 5, lane = tid & 31;
    int bm = blockIdx.y * 128, bn = blockIdx.x * 128;
    int wm = (wid & 3) * 32, wn = (wid >> 2) * 64;
    const int S = (3 * K) >> 6;

    int arow = tid >> 3, acol = (tid & 7) * 8;

    float acc[2][8][4];
    #pragma unroll
    for (int i = 0; i < 2; i++)
        #pragma unroll
        for (int j = 0; j < 8; j++)
            #pragma unroll
            for (int q = 0; q < 4; q++) acc[i][j][q] = 0.0f;

    auto issue = [&](int s) {
        int k0 = s << 6;
        int blk = k0 / K, cin = k0 - blk * K;
        int acb = ((blk == 1) ? K : 0) + cin;
        int bcb = ((blk == 2) ? K : 0) + cin;
        int st = s % 3;
        uint32_t sa = smb + st * STG;
        uint32_t sb = smb + 3 * STG + st * STG;
        #pragma unroll
        for (int p = 0; p < 4; p++) {
            int r = p * 32 + arow;
            cp16(sa + r * (MSTRIDE * 2) + acol * 2,
                 A + (size_t)(bm + r) * ldA + acb + acol);
            cp16(sb + r * (MSTRIDE * 2) + acol * 2,
                 B + (size_t)(bn + r) * ldB + bcb + acol);
        }
        asm volatile("cp.async.commit_group;" ::: "memory");
    };

    issue(0);
    issue(1);
    for (int s = 0; s < S; s++) {
        if (s + 2 < S) {
            asm volatile("cp.async.wait_group 1;" ::: "memory");
        } else {
            asm volatile("cp.async.wait_group 0;" ::: "memory");
        }
        __syncthreads();
        if (s + 2 < S) issue(s + 2);
        int st = s % 3;
        uint32_t sa = smb + st * STG;
        uint32_t sb = smb + 3 * STG + st * STG;
        #pragma unroll
        for (int kk = 0; kk < 4; kk++) {
            uint32_t a[2][4], bfr[4][4];
            #pragma unroll
            for (int f = 0; f < 2; f++) {
                int row = wm + f * 16 + (lane & 15);
                uint32_t addr = sa + row * (MSTRIDE * 2) +
                                kk * 32 + ((lane >> 4) << 4);
                ldm4(addr, a[f][0], a[f][1], a[f][2], a[f][3]);
            }
            #pragma unroll
            for (int g = 0; g < 4; g++) {
                int row = wn + g * 16 + (lane & 7) + (((lane >> 4) & 1) << 3);
                uint32_t addr = sb + row * (MSTRIDE * 2) +
                                kk * 32 + (((lane >> 3) & 1) << 4);
                ldm4(addr, bfr[g][0], bfr[g][1], bfr[g][2], bfr[g][3]);
            }
            #pragma unroll
            for (int f = 0; f < 2; f++)
                #pragma unroll
                for (int nf = 0; nf < 8; nf++)
                    mma16816(acc[f][nf], a[f],
                             bfr[nf >> 1][(nf & 1) * 2],
                             bfr[nf >> 1][(nf & 1) * 2 + 1]);
        }
    }

    #pragma unroll
    for (int f = 0; f < 2; f++) {
        int r0 = bm + wm + f * 16 + (lane >> 2);
        #pragma unroll
        for (int nf = 0; nf < 8; nf++) {
            int c = bn + wn + nf * 8 + (lane & 3) * 2;
            float* d = acc[f][nf];
            #pragma unroll
            for (int half = 0; half < 2; half++) {
                int r = r0 + half * 8;
                float v0 = d[half * 2 + 0];
                float v1 = d[half * 2 + 1];
                if (EPI == 0) {
                    *(float2*)&Cf[(size_t)r * ldc + c] = make_float2(v0, v1);
                } else if (EPI == 1) {
                    v0 += bias[c]     + res[(size_t)r * ldres + c];
                    v1 += bias[c + 1] + res[(size_t)r * ldres + c + 1];
                    *(float2*)&Cf[(size_t)r * ldc + c] = make_float2(v0, v1);
                } else {
                    if (EPI == 2) {
                        v0 += bias[c];
                        v1 += bias[c + 1];
                        v0 = 0.5f * v0 * (1.0f + erff(v0 * 0.70710678118654752f));
                        v1 = 0.5f * v1 * (1.0f + erff(v1 * 0.70710678118654752f));
                    }
                    __nv_bfloat16 h0, l0, h1, l1;
                    bf16split(v0, h0, l0);
                    bf16split(v1, h1, l1);
                    *(__nv_bfloat162*)&Cb[(size_t)r * ldc + c] =
                        __halves2bfloat162(h0, h1);
                    *(__nv_bfloat162*)&Cb[(size_t)r * ldc + khalf + c] =
                        __halves2bfloat162(l0, l1);
                }
            }
        }
    }
}

// ------------------------- HMMA flash attention ----------------------------
// 128 threads / 4 warps; cp.async double-buffered K/V, one sync per k-tile.
#define FROW 72
#define FMAT (64 * FROW)                 // bf16 elements per smem matrix
#define FMATB (FMAT * 2)                 // bytes = 9216
#define FB_SMEM (2 * FMATB + 2 * 4 * FMATB)   // Q(2) + 2 stages x (Kh,Kl,Vh,Vl)
__global__ void __launch_bounds__(128) flashT_kernel(
    const __nv_bfloat16* __restrict__ qkvb, __nv_bfloat16* __restrict__ oA) {
    extern __shared__ __nv_bfloat16 fsm[];
    uint32_t smb = smem_u32(fsm);
    uint32_t sQh = smb, sQl = smb + FMATB;

    int ti = blockIdx.x, bh = blockIdx.y;
    int b = bh >> 4, h = bh & 15;
    int t0 = ti * 64;
    int tid = threadIdx.x, wid = tid >> 5, lane = tid & 31;
    const int ld = 6 * TD;

    const __nv_bfloat16* rowbase = qkvb + (size_t)(b * TT) * ld;
    const __nv_bfloat16* Qhg = rowbase + (size_t)t0 * ld + h * THD;
    const __nv_bfloat16* Khg = rowbase + TD + h * THD;
    const __nv_bfloat16* Vhg = rowbase + 2 * TD + h * THD;

    // async copy one 64x64 bf16 matrix into smem (4 cp16 per thread)
    auto cpmat = [&](uint32_t sdst, const __nv_bfloat16* src) {
        #pragma unroll
        for (int it = 0; it < 4; it++) {
            int u = it * 128 + tid;
            int r = u >> 3, q = u & 7;
            cp16(sdst + (r * FROW + q * 8) * 2, src + (size_t)r * ld + q * 8);
        }
    };
    auto issueKV = [&](int sj) {
        int st = sj & 1;
        uint32_t base = smb + 2 * FMATB + st * 4 * FMATB;
        const __nv_bfloat16* Ksrc = Khg + (size_t)(sj * 64) * ld;
        const __nv_bfloat16* Vsrc = Vhg + (size_t)(sj * 64) * ld;
        cpmat(base, Ksrc);
        cpmat(base + FMATB, Ksrc + 3 * TD);
        cpmat(base + 2 * FMATB, Vsrc);
        cpmat(base + 3 * FMATB, Vsrc + 3 * TD);
        asm volatile("cp.async.commit_group;" ::: "memory");
    };

    // prologue: Q + KV(0) in one group
    cpmat(sQh, Qhg);
    cpmat(sQl, Qhg + 3 * TD);
    {
        int st = 0;
        uint32_t base = smb + 2 * FMATB + st * 4 * FMATB;
        cpmat(base, Khg);
        cpmat(base + FMATB, Khg + 3 * TD);
        cpmat(base + 2 * FMATB, Vhg);
        cpmat(base + 3 * FMATB, Vhg + 3 * TD);
    }
    asm volatile("cp.async.commit_group;" ::: "memory");
    asm volatile("cp.async.wait_group 0;" ::: "memory");
    __syncthreads();

    // Q register fragments
    uint32_t qh[4][4], ql[4][4];
    {
        int row = wid * 16 + (lane & 15);
        #pragma unroll
        for (int kk = 0; kk < 4; kk++) {
            uint32_t off = row * (FROW * 2) + kk * 32 + ((lane >> 4) << 4);
            ldm4(sQh + off, qh[kk][0], qh[kk][1], qh[kk][2], qh[kk][3]);
            ldm4(sQl + off, ql[kk][0], ql[kk][1], ql[kk][2], ql[kk][3]);
        }
    }

    float oacc[8][4];
    #pragma unroll
    for (int nf = 0; nf < 8; nf++)
        #pragma unroll
        for (int q = 0; q < 4; q++) oacc[nf][q] = 0.0f;
    float m0 = -1e30f, m1 = -1e30f, l0 = 0.0f, l1 = 0.0f;

    for (int sj = 0; sj <= ti; sj++) {
        // overlap: next KV tile loads while we compute this one
        if (sj + 1 <= ti) issueKV(sj + 1);

        int st = sj & 1;
        uint32_t kvb = smb + 2 * FMATB + st * 4 * FMATB;
        uint32_t sKh = kvb, sKl = kvb + FMATB;
        uint32_t sVh = kvb + 2 * FMATB, sVl = kvb + 3 * FMATB;

        // ---- S = Q K^T (3 split terms) ----
        float sacc[8][4];
        #pragma unroll
        for (int nf = 0; nf < 8; nf++)
            #pragma unroll
            for (int q = 0; q < 4; q++) sacc[nf][q] = 0.0f;
        #pragma unroll
        for (int kk = 0; kk < 4; kk++) {
            uint32_t bh4[4][4], bl4[4][4];
            int row = (lane & 7) + (((lane >> 4) & 1) << 3);
            uint32_t coff = kk * 32 + (((lane >> 3) & 1) << 4);
            #pragma unroll
            for (int g = 0; g < 4; g++) {
                uint32_t off = (g * 16 + row) * (FROW * 2) + coff;
                ldm4(sKh + off, bh4[g][0], bh4[g][1], bh4[g][2], bh4[g][3]);
                ldm4(sKl + off, bl4[g][0], bl4[g][1], bl4[g][2], bl4[g][3]);
            }
            #pragma unroll
            for (int nf = 0; nf < 8; nf++) {
                uint32_t b0 = bh4[nf >> 1][(nf & 1) * 2];
                uint32_t b1 = bh4[nf >> 1][(nf & 1) * 2 + 1];
                mma16816(sacc[nf], qh[kk], b0, b1);
                mma16816(sacc[nf], ql[kk], b0, b1);
                mma16816(sacc[nf], qh[kk],
                         bl4[nf >> 1][(nf & 1) * 2],
                         bl4[nf >> 1][(nf & 1) * 2 + 1]);
            }
        }

        // ---- scale + causal mask ----
        bool diag = (sj == ti);
        int rloc0 = wid * 16 + (lane >> 2);
        #pragma unroll
        for (int nf = 0; nf < 8; nf++) {
            #pragma unroll
            for (int q = 0; q < 4; q++) {
                float v = sacc[nf][q] * 0.125f;
                if (diag) {
                    int col = nf * 8 + (lane & 3) * 2 + (q & 1);
                    int rr = rloc0 + (q >> 1) * 8;
                    if (col > rr) v = -1e30f;
                }
                sacc[nf][q] = v;
            }
        }

        // ---- online softmax (quad-lane reduction) ----
        float mx0 = -1e30f, mx1 = -1e30f;
        #pragma unroll
        for (int nf = 0; nf < 8; nf++) {
            mx0 = fmaxf(mx0, fmaxf(sacc[nf][0], sacc[nf][1]));
            mx1 = fmaxf(mx1, fmaxf(sacc[nf][2], sacc[nf][3]));
        }
        #pragma unroll
        for (int o = 1; o <= 2; o <<= 1) {
            mx0 = fmaxf(mx0, __shfl_xor_sync(0xffffffffu, mx0, o));
            mx1 = fmaxf(mx1, __shfl_xor_sync(0xffffffffu, mx1, o));
        }
        float mn0 = fmaxf(m0, mx0), mn1 = fmaxf(m1, mx1);
        float sc0 = __expf(m0 - mn0), sc1 = __expf(m1 - mn1);
        float rs0 = 0.0f, rs1 = 0.0f;
        #pragma unroll
        for (int nf = 0; nf < 8; nf++) {
            sacc[nf][0] = __expf(sacc[nf][0] - mn0);
            sacc[nf][1] = __expf(sacc[nf][1] - mn0);
            sacc[nf][2] = __expf(sacc[nf][2] - mn1);
            sacc[nf][3] = __expf(sacc[nf][3] - mn1);
            rs0 += sacc[nf][0] + sacc[nf][1];
            rs1 += sacc[nf][2] + sacc[nf][3];
        }
        #pragma unroll
        for (int o = 1; o <= 2; o <<= 1) {
            rs0 += __shfl_xor_sync(0xffffffffu, rs0, o);
            rs1 += __shfl_xor_sync(0xffffffffu, rs1, o);
        }
        l0 = l0 * sc0 + rs0; l1 = l1 * sc1 + rs1;
        m0 = mn0; m1 = mn1;
        #pragma unroll
        for (int nf = 0; nf < 8; nf++) {
            oacc[nf][0] *= sc0; oacc[nf][1] *= sc0;
            oacc[nf][2] *= sc1; oacc[nf][3] *= sc1;
        }

        // ---- O += P @ V (P repacked in registers, 3 split terms) ----
        #pragma unroll
        for (int kk = 0; kk < 4; kk++) {
            float* p0 = sacc[2 * kk];
            float* p1 = sacc[2 * kk + 1];
            uint32_t aPh[4], aPl[4];
            {
                __nv_bfloat16 hh, llv;
                float r00, r01, r10, r11;
                bf16split(p0[0], hh, llv); r00 = __bfloat162float(llv);
                bf16split(p0[1], hh, llv); r01 = __bfloat162float(llv);
                aPh[0] = packbf2(p0[0], p0[1]); aPl[0] = packbf2(r00, r01);
                bf16split(p0[2], hh, llv); r10 = __bfloat162float(llv);
                bf16split(p0[3], hh, llv); r11 = __bfloat162float(llv);
                aPh[1] = packbf2(p0[2], p0[3]); aPl[1] = packbf2(r10, r11);
                bf16split(p1[0], hh, llv); r00 = __bfloat162float(llv);
                bf16split(p1[1], hh, llv); r01 = __bfloat162float(llv);
                aPh[2] = packbf2(p1[0], p1[1]); aPl[2] = packbf2(r00, r01);
                bf16split(p1[2], hh, llv); r10 = __bfloat162float(llv);
                bf16split(p1[3], hh, llv); r11 = __bfloat162float(llv);
                aPh[3] = packbf2(p1[2], p1[3]); aPl[3] = packbf2(r10, r11);
            }
            uint32_t vh4[4][4], vl4[4][4];
            int srow = kk * 16 + (lane & 15);
            #pragma unroll
            for (int g = 0; g < 4; g++) {
                uint32_t off = srow * (FROW * 2) +
                               (g * 16 + ((lane >> 4) << 3)) * 2;
                ldm4t(sVh + off, vh4[g][0], vh4[g][1], vh4[g][2], vh4[g][3]);
                ldm4t(sVl + off, vl4[g][0], vl4[g][1], vl4[g][2], vl4[g][3]);
            }
            #pragma unroll
            for (int nf = 0; nf < 8; nf++) {
                uint32_t b0 = vh4[nf >> 1][(nf & 1) * 2];
                uint32_t b1 = vh4[nf >> 1][(nf & 1) * 2 + 1];
                mma16816(oacc[nf], aPh, b0, b1);
                mma16816(oacc[nf], aPl, b0, b1);
                mma16816(oacc[nf], aPh,
                         vl4[nf >> 1][(nf & 1) * 2],
                         vl4[nf >> 1][(nf & 1) * 2 + 1]);
            }
        }

        // wait for next tile + make it visible; protects stage reuse
        if (sj + 1 <= ti) {
            asm volatile("cp.async.wait_group 0;" ::: "memory");
            __syncthreads();
        }
    }

    // ---- finalize + split-bf16 store ----
    float inv0 = 1.0f / l0, inv1 = 1.0f / l1;
    int r0 = t0 + wid * 16 + (lane >> 2);
    #pragma unroll
    for (int nf = 0; nf < 8; nf++) {
        int d = nf * 8 + (lane & 3) * 2;
        __nv_bfloat16* base0 =
            oA + (size_t)(b * TT + r0) * (2 * TD) + h * THD + d;
        __nv_bfloat16* base1 =
            oA + (size_t)(b * TT + r0 + 8) * (2 * TD) + h * THD + d;
        __nv_bfloat16 h0, lo0, h1, lo1;
        bf16split(oacc[nf][0] * inv0, h0, lo0);
        bf16split(oacc[nf][1] * inv0, h1, lo1);
        *(__nv_bfloat162*)base0 = __halves2bfloat162(h0, h1);
        *(__nv_bfloat162*)(base0 + TD) = __halves2bfloat162(lo0, lo1);
        bf16split(oacc[nf][2] * inv1, h0, lo0);
        bf16split(oacc[nf][3] * inv1, h1, lo1);
        *(__nv_bfloat162*)base1 = __halves2bfloat162(h0, h1);
        *(__nv_bfloat162*)(base1 + TD) = __halves2bfloat162(lo0, lo1);
    }
}

// ------------------------- launch ------------------------------------------
extern "C" void kernel_launch(void* const* d_in, const int* in_sizes, int n_in,
                              void* d_out, int out_size) {
    const float* x   = (const float*)d_in[0];
    const float* Wq  = (const float*)d_in[1];
    const float* Wk  = (const float*)d_in[2];
    const float* Wv  = (const float*)d_in[3];
    const float* Wo  = (const float*)d_in[4];
    const float* bo  = (const float*)d_in[5];
    const float* W1  = (const float*)d_in[6];
    const float* b1  = (const float*)d_in[7];
    const float* W2  = (const float*)d_in[8];
    const float* b2  = (const float*)d_in[9];
    const float* g1  = (const float*)d_in[10];
    const float* be1 = (const float*)d_in[11];
    const float* g2  = (const float*)d_in[12];
    const float* be2 = (const float*)d_in[13];
    float* out = (float*)d_out;

    __nv_bfloat16 *hA, *qkvb, *oA, *ffA, *wqkv, *wo, *w1, *w2;
    float *x2;
    cudaGetSymbolAddress((void**)&hA,   g_hA);
    cudaGetSymbolAddress((void**)&qkvb, g_qkvb);
    cudaGetSymbolAddress((void**)&oA,   g_oA);
    cudaGetSymbolAddress((void**)&x2,   g_x2);
    cudaGetSymbolAddress((void**)&ffA,  g_ffA);
    cudaGetSymbolAddress((void**)&wqkv, g_wqkv);
    cudaGetSymbolAddress((void**)&wo,   g_wo);
    cudaGetSymbolAddress((void**)&w1,   g_w1);
    cudaGetSymbolAddress((void**)&w2,   g_w2);

    static int attr_set = 0;
    if (!attr_set) {
        cudaFuncSetAttribute(flashT_kernel,
                             cudaFuncAttributeMaxDynamicSharedMemorySize, FB_SMEM);
        cudaFuncSetAttribute(mgemm_kernel<0>,
                             cudaFuncAttributeMaxDynamicSharedMemorySize, MDYN);
        cudaFuncSetAttribute(mgemm_kernel<1>,
                             cudaFuncAttributeMaxDynamicSharedMemorySize, MDYN);
        cudaFuncSetAttribute(mgemm_kernel<2>,
                             cudaFuncAttributeMaxDynamicSharedMemorySize, MDYN);
        cudaFuncSetAttribute(mgemm_kernel<3>,
                             cudaFuncAttributeMaxDynamicSharedMemorySize, MDYN);
        attr_set = 1;
    }

    dim3 cb(32, 8);
    qkvconv_kernel<<<dim3(2, 32, 48), cb>>>(Wq, Wk, Wv, wqkv);
    wconv_kernel<<<dim3(32, 32), cb>>>(Wo, TD, wo, 2 * TD, TD);
    wconv_kernel<<<dim3(128, 32), cb>>>(W1, TDFF, w1, 2 * TD, TD);
    wconv_kernel<<<dim3(32, 128), cb>>>(W2, TD, w2, 2 * TDFF, TDFF);

    // LN1 -> split operand
    ln_kernel<<<BT, 256>>>(x, g1, be1, hA);
    // QKV GEMM -> split bf16 output (attention operands)
    mgemm_kernel<3><<<dim3(24, 32), 256, MDYN>>>(
        hA, wqkv, nullptr, qkvb, TD, 2 * TD, 2 * TD, 6 * TD, 3 * TD,
        nullptr, nullptr, 0);
    // HMMA flash attention -> split operand
    flashT_kernel<<<dim3(32, TB * TH), 128, FB_SMEM>>>(qkvb, oA);
    // x2 = x + o @ Wo + bo
    mgemm_kernel<1><<<dim3(8, 32), 256, MDYN>>>(
        oA, wo, x2, nullptr, TD, 2 * TD, 2 * TD, TD, 0, bo, x, TD);
    // LN2 -> split operand
    ln_kernel<<<BT, 256>>>(x2, g2, be2, hA);
    // ff = gelu(h2 @ W1 + b1) -> split operand
    mgemm_kernel<2><<<dim3(32, 32), 256, MDYN>>>(
        hA, w1, nullptr, ffA, TD, 2 * TD, 2 * TD, 2 * TDFF, TDFF,
        b1, nullptr, 0);
    // out = x2 + ff @ W2 + b2
    mgemm_kernel<1><<<dim3(8, 32), 256, MDYN>>>(
        ffA, w2, out, nullptr, TDFF, 2 * TDFF, 2 * TDFF, TD, 0, b2, x2, TD);
}

// round 11
// speedup vs baseline: 1.2527x; 1.2527x over previous
#include <cuda_runtime.h>
#include <cuda_bf16.h>
#include <math.h>
#include <stdint.h>

// Problem dims
#define TB   2
#define TT   2048
#define TD   1024
#define TH   16
#define THD  64
#define TDFF 4096
#define BT   (TB*TT)

// ------------------------- scratch (device globals) ------------------------
__device__ __nv_bfloat16 g_hA  [(size_t)BT * 2 * TD];     // LN out, split
__device__ __nv_bfloat16 g_qkvb[(size_t)BT * 6 * TD];     // qkv split: hi 3TD | lo 3TD
__device__ __nv_bfloat16 g_oA  [(size_t)BT * 2 * TD];     // attn out, split
__device__ float         g_x2  [(size_t)BT * TD];
__device__ __nv_bfloat16 g_ffA [(size_t)BT * 2 * TDFF];
// B-operands (weights), K-major [N][2K]: (hi | lo)
__device__ __nv_bfloat16 g_wqkv[(size_t)(3*TD) * (2*TD)];
__device__ __nv_bfloat16 g_wo  [(size_t)TD * (2*TD)];
__device__ __nv_bfloat16 g_w1  [(size_t)TDFF * (2*TD)];
__device__ __nv_bfloat16 g_w2  [(size_t)TD * (2*TDFF)];

__device__ __forceinline__ uint32_t smem_u32(const void* p) {
    uint32_t a;
    asm("{ .reg .u64 t; cvta.to.shared.u64 t, %1; cvt.u32.u64 %0, t; }"
        : "=r"(a) : "l"(p));
    return a;
}
__device__ __forceinline__ void bf16split(float v, __nv_bfloat16& hi,
                                          __nv_bfloat16& lo) {
    hi = __float2bfloat16(v);
    lo = __float2bfloat16(v - __bfloat162float(hi));
}
__device__ __forceinline__ uint32_t packbf2(float x, float y) {
    __nv_bfloat162 t = __floats2bfloat162_rn(x, y);
    return *(uint32_t*)&t;
}
__device__ __forceinline__ void cp16(uint32_t sdst, const void* gsrc) {
    asm volatile("cp.async.cg.shared.global [%0], [%1], 16;"
                 :: "r"(sdst), "l"(gsrc));
}
__device__ __forceinline__ void ldm4(uint32_t addr, uint32_t& r0, uint32_t& r1,
                                     uint32_t& r2, uint32_t& r3) {
    asm volatile("ldmatrix.sync.aligned.m8n8.x4.shared.b16 {%0,%1,%2,%3}, [%4];"
                 : "=r"(r0), "=r"(r1), "=r"(r2), "=r"(r3) : "r"(addr));
}
__device__ __forceinline__ void ldm4t(uint32_t addr, uint32_t& r0, uint32_t& r1,
                                      uint32_t& r2, uint32_t& r3) {
    asm volatile("ldmatrix.sync.aligned.m8n8.x4.trans.shared.b16 {%0,%1,%2,%3}, [%4];"
                 : "=r"(r0), "=r"(r1), "=r"(r2), "=r"(r3) : "r"(addr));
}
__device__ __forceinline__ void mma16816(float* d, const uint32_t* a,
                                         uint32_t b0, uint32_t b1) {
    asm volatile(
        "mma.sync.aligned.m16n8k16.row.col.f32.bf16.bf16.f32 "
        "{%0,%1,%2,%3}, {%4,%5,%6,%7}, {%8,%9}, {%0,%1,%2,%3};"
        : "+f"(d[0]), "+f"(d[1]), "+f"(d[2]), "+f"(d[3])
        : "r"(a[0]), "r"(a[1]), "r"(a[2]), "r"(a[3]), "r"(b0), "r"(b1));
}

// ------------------------- weight convert (tiled transpose + split) --------
__global__ void __launch_bounds__(256) wconv_kernel(
    const float* __restrict__ src, int srcld,
    __nv_bfloat16* __restrict__ dst, int dstld, int khalf) {
    __shared__ float t[32][33];
    int k0 = blockIdx.y * 32, n0 = blockIdx.x * 32;
    int tx = threadIdx.x, ty = threadIdx.y;
    #pragma unroll
    for (int i = 0; i < 4; i++)
        t[ty + 8 * i][tx] = src[(size_t)(k0 + ty + 8 * i) * srcld + n0 + tx];
    __syncthreads();
    #pragma unroll
    for (int i = 0; i < 4; i++) {
        int n = n0 + ty + 8 * i, k = k0 + tx;
        __nv_bfloat16 hi, lo;
        bf16split(t[tx][ty + 8 * i], hi, lo);
        dst[(size_t)n * dstld + k] = hi;
        dst[(size_t)n * dstld + khalf + k] = lo;
    }
}

__global__ void __launch_bounds__(256) qkvconv_kernel(
    const float* __restrict__ Wq, const float* __restrict__ Wk,
    const float* __restrict__ Wv, __nv_bfloat16* __restrict__ dst) {
    __shared__ float t[32][33];
    int z = blockIdx.z;
    int third = z >> 4, h = z & 15;
    const float* W = (third == 0) ? Wq : ((third == 1) ? Wk : Wv);
    const float* src = W + (size_t)h * TD * THD;
    int k0 = blockIdx.y * 32, n0 = blockIdx.x * 32;
    int tx = threadIdx.x, ty = threadIdx.y;
    #pragma unroll
    for (int i = 0; i < 4; i++)
        t[ty + 8 * i][tx] = src[(size_t)(k0 + ty + 8 * i) * THD + n0 + tx];
    __syncthreads();
    #pragma unroll
    for (int i = 0; i < 4; i++) {
        int nl = n0 + ty + 8 * i, k = k0 + tx;
        int n = third * TD + h * THD + nl;
        __nv_bfloat16 hi, lo;
        bf16split(t[tx][ty + 8 * i], hi, lo);
        dst[(size_t)n * (2 * TD) + k] = hi;
        dst[(size_t)n * (2 * TD) + TD + k] = lo;
    }
}

// ------------------------- LayerNorm -> split bf16 A operand ---------------
__global__ void __launch_bounds__(256) ln_kernel(const float* __restrict__ x,
                                                 const float* __restrict__ g,
                                                 const float* __restrict__ b,
                                                 __nv_bfloat16* __restrict__ outA) {
    __shared__ float sh[16];
    int row = blockIdx.x;
    int tid = threadIdx.x;
    const float* xr = x + (size_t)row * TD;
    float4 v = *(const float4*)(xr + tid * 4);
    float s  = v.x + v.y + v.z + v.w;
    float sq = v.x * v.x + v.y * v.y + v.z * v.z + v.w * v.w;
    #pragma unroll
    for (int o = 16; o; o >>= 1) {
        s  += __shfl_xor_sync(0xffffffffu, s, o);
        sq += __shfl_xor_sync(0xffffffffu, sq, o);
    }
    if ((tid & 31) == 0) { sh[tid >> 5] = s; sh[(tid >> 5) + 8] = sq; }
    __syncthreads();
    if (tid < 32) {
        float a = (tid < 8) ? sh[tid] : 0.0f;
        float c = (tid < 8) ? sh[tid + 8] : 0.0f;
        #pragma unroll
        for (int o = 4; o; o >>= 1) {
            a += __shfl_xor_sync(0xffffffffu, a, o);
            c += __shfl_xor_sync(0xffffffffu, c, o);
        }
        if (tid == 0) { sh[0] = a; sh[1] = c; }
    }
    __syncthreads();
    float mu  = sh[0] * (1.0f / TD);
    float var = sh[1] * (1.0f / TD) - mu * mu;
    float rs  = rsqrtf(var + 1e-5f);
    float4 gg = *(const float4*)(g + tid * 4);
    float4 bb = *(const float4*)(b + tid * 4);
    float o0 = (v.x - mu) * rs * gg.x + bb.x;
    float o1 = (v.y - mu) * rs * gg.y + bb.y;
    float o2 = (v.z - mu) * rs * gg.z + bb.z;
    float o3 = (v.w - mu) * rs * gg.w + bb.w;
    __nv_bfloat16 h0, l0, h1, l1, h2, l2, h3, l3;
    bf16split(o0, h0, l0); bf16split(o1, h1, l1);
    bf16split(o2, h2, l2); bf16split(o3, h3, l3);
    __nv_bfloat16* base = outA + (size_t)row * (2 * TD) + tid * 4;
    *(__nv_bfloat162*)(base + 0) = __halves2bfloat162(h0, h1);
    *(__nv_bfloat162*)(base + 2) = __halves2bfloat162(h2, h3);
    *(__nv_bfloat162*)(base + TD + 0) = __halves2bfloat162(l0, l1);
    *(__nv_bfloat162*)(base + TD + 2) = __halves2bfloat162(l2, l3);
}

// ------------------------- HMMA split-bf16 GEMM ----------------------------
// Fused-term schedule: each 32-k stage loads [Ah|Al] and [Bh|Bl] slabs
// (64-wide rows, same smem as R9) and computes Ah*Bh + Al*Bh + Ah*Bl.
// 2-stage cp.async double buffer, 2 CTAs/SM.
// EPI: 0 fp32; 1 +bias+res fp32; 2 +bias GELU split-bf16; 3 plain split-bf16
#define MSTRIDE 72
#define STG     (128 * MSTRIDE * 2)     // 18432 B per operand stage
#define MDYN    (4 * STG)               // 73728 B

template <int EPI>
__global__ void __launch_bounds__(256, 2) mgemm_kernel(
    const __nv_bfloat16* __restrict__ A, const __nv_bfloat16* __restrict__ B,
    float* __restrict__ Cf, __nv_bfloat16* __restrict__ Cb,
    int K, int ldA, int ldB, int ldc, int khalf,
    const float* __restrict__ bias, const float* __restrict__ res, int ldres) {
    extern __shared__ char smp[];
    uint32_t smb = smem_u32(smp);
    int tid = threadIdx.x, wid = tid >> 5, lane = tid & 31;
    int bm = blockIdx.y * 128, bn = blockIdx.x * 128;
    int wm = (wid & 3) * 32, wn = (wid >> 2) * 64;
    const int S = K >> 5;               // 32 logical k per stage, 3 terms each

    int arow = tid >> 3, acol = (tid & 7) * 8;

    float acc[2][8][4];
    #pragma unroll
    for (int i = 0; i < 2; i++)
        #pragma unroll
        for (int j = 0; j < 8; j++)
            #pragma unroll
            for (int q = 0; q < 4; q++) acc[i][j][q] = 0.0f;

    // stage s: A slab rows hold [Ah(32) | Al(32)], B slab [Bh(32) | Bl(32)]
    auto issue = [&](int s) {
        int k0 = s << 5;
        int col = (acol < 32) ? (k0 + acol) : (K + k0 + (acol - 32));
        int st = s & 1;
        uint32_t sa = smb + st * STG;
        uint32_t sb = smb + 2 * STG + st * STG;
        #pragma unroll
        for (int p = 0; p < 4; p++) {
            int r = p * 32 + arow;
            cp16(sa + r * (MSTRIDE * 2) + acol * 2,
                 A + (size_t)(bm + r) * ldA + col);
            cp16(sb + r * (MSTRIDE * 2) + acol * 2,
                 B + (size_t)(bn + r) * ldB + col);
        }
        asm volatile("cp.async.commit_group;" ::: "memory");
    };

    issue(0);
    for (int s = 0; s < S; s++) {
        if (s + 1 < S) {
            issue(s + 1);
            asm volatile("cp.async.wait_group 1;" ::: "memory");
        } else {
            asm volatile("cp.async.wait_group 0;" ::: "memory");
        }
        __syncthreads();
        int st = s & 1;
        uint32_t sa = smb + st * STG;
        uint32_t sb = smb + 2 * STG + st * STG;
        #pragma unroll
        for (int kk = 0; kk < 2; kk++) {
            uint32_t ah[2][4], al[2][4], bh[4][4], bl[4][4];
            #pragma unroll
            for (int f = 0; f < 2; f++) {
                int row = wm + f * 16 + (lane & 15);
                uint32_t addr = sa + row * (MSTRIDE * 2) +
                                kk * 32 + ((lane >> 4) << 4);
                ldm4(addr, ah[f][0], ah[f][1], ah[f][2], ah[f][3]);
                ldm4(addr + 64, al[f][0], al[f][1], al[f][2], al[f][3]);
            }
            #pragma unroll
            for (int g = 0; g < 4; g++) {
                int row = wn + g * 16 + (lane & 7) + (((lane >> 4) & 1) << 3);
                uint32_t addr = sb + row * (MSTRIDE * 2) +
                                kk * 32 + (((lane >> 3) & 1) << 4);
                ldm4(addr, bh[g][0], bh[g][1], bh[g][2], bh[g][3]);
            }
            #pragma unroll
            for (int f = 0; f < 2; f++)
                #pragma unroll
                for (int nf = 0; nf < 8; nf++) {
                    uint32_t b0 = bh[nf >> 1][(nf & 1) * 2];
                    uint32_t b1 = bh[nf >> 1][(nf & 1) * 2 + 1];
                    mma16816(acc[f][nf], ah[f], b0, b1);
                    mma16816(acc[f][nf], al[f], b0, b1);
                }
            #pragma unroll
            for (int g = 0; g < 4; g++) {
                int row = wn + g * 16 + (lane & 7) + (((lane >> 4) & 1) << 3);
                uint32_t addr = sb + row * (MSTRIDE * 2) +
                                kk * 32 + (((lane >> 3) & 1) << 4);
                ldm4(addr + 64, bl[g][0], bl[g][1], bl[g][2], bl[g][3]);
            }
            #pragma unroll
            for (int f = 0; f < 2; f++)
                #pragma unroll
                for (int nf = 0; nf < 8; nf++)
                    mma16816(acc[f][nf], ah[f],
                             bl[nf >> 1][(nf & 1) * 2],
                             bl[nf >> 1][(nf & 1) * 2 + 1]);
        }
        __syncthreads();
    }

    #pragma unroll
    for (int f = 0; f < 2; f++) {
        int r0 = bm + wm + f * 16 + (lane >> 2);
        #pragma unroll
        for (int nf = 0; nf < 8; nf++) {
            int c = bn + wn + nf * 8 + (lane & 3) * 2;
            float* d = acc[f][nf];
            #pragma unroll
            for (int half = 0; half < 2; half++) {
                int r = r0 + half * 8;
                float v0 = d[half * 2 + 0];
                float v1 = d[half * 2 + 1];
                if (EPI == 0) {
                    *(float2*)&Cf[(size_t)r * ldc + c] = make_float2(v0, v1);
                } else if (EPI == 1) {
                    v0 += bias[c]     + res[(size_t)r * ldres + c];
                    v1 += bias[c + 1] + res[(size_t)r * ldres + c + 1];
                    *(float2*)&Cf[(size_t)r * ldc + c] = make_float2(v0, v1);
                } else {
                    if (EPI == 2) {
                        v0 += bias[c];
                        v1 += bias[c + 1];
                        v0 = 0.5f * v0 * (1.0f + erff(v0 * 0.70710678118654752f));
                        v1 = 0.5f * v1 * (1.0f + erff(v1 * 0.70710678118654752f));
                    }
                    __nv_bfloat16 h0, l0, h1, l1;
                    bf16split(v0, h0, l0);
                    bf16split(v1, h1, l1);
                    *(__nv_bfloat162*)&Cb[(size_t)r * ldc + c] =
                        __halves2bfloat162(h0, h1);
                    *(__nv_bfloat162*)&Cb[(size_t)r * ldc + khalf + c] =
                        __halves2bfloat162(l0, l1);
                }
            }
        }
    }
}

// ------------------------- HMMA flash attention (R9 shape) -----------------
#define FROW 72
#define FMAT (64 * FROW)                 // bf16 elements per smem matrix
#define FB_SMEM (6 * FMAT * 2)           // Qh Ql Kh Kl Vh Vl = 55296 B
__global__ void __launch_bounds__(128) flashT_kernel(
    const __nv_bfloat16* __restrict__ qkvb, __nv_bfloat16* __restrict__ oA) {
    extern __shared__ __nv_bfloat16 fsm[];
    __nv_bfloat16* Qh = fsm;
    __nv_bfloat16* Ql = fsm + FMAT;
    __nv_bfloat16* Kh = fsm + 2 * FMAT;
    __nv_bfloat16* Kl = fsm + 3 * FMAT;
    __nv_bfloat16* Vh = fsm + 4 * FMAT;
    __nv_bfloat16* Vl = fsm + 5 * FMAT;
    uint32_t sKh = smem_u32(Kh), sKl = smem_u32(Kl);
    uint32_t sVh = smem_u32(Vh), sVl = smem_u32(Vl);

    int ti = blockIdx.x, bh = blockIdx.y;
    int b = bh >> 4, h = bh & 15;
    int t0 = ti * 64;
    int tid = threadIdx.x, wid = tid >> 5, lane = tid & 31;
    const int ld = 6 * TD;

    const __nv_bfloat16* rowbase = qkvb + (size_t)(b * TT) * ld;
    const __nv_bfloat16* Qhg = rowbase + (size_t)t0 * ld + h * THD;
    const __nv_bfloat16* Khg = rowbase + TD + h * THD;
    const __nv_bfloat16* Vhg = rowbase + 2 * TD + h * THD;

    auto copy6464 = [&](__nv_bfloat16* dst, const __nv_bfloat16* src) {
        #pragma unroll
        for (int it = 0; it < 4; it++) {
            int u = it * 128 + tid;
            int r = u >> 3, q = u & 7;
            *(uint4*)&dst[r * FROW + q * 8] =
                *(const uint4*)(src + (size_t)r * ld + q * 8);
        }
    };

    copy6464(Qh, Qhg);
    copy6464(Ql, Qhg + 3 * TD);
    __syncthreads();
    uint32_t qh[4][4], ql[4][4];
    {
        uint32_t sQh = smem_u32(Qh), sQl = smem_u32(Ql);
        int row = wid * 16 + (lane & 15);
        #pragma unroll
        for (int kk = 0; kk < 4; kk++) {
            uint32_t off = row * (FROW * 2) + kk * 32 + ((lane >> 4) << 4);
            ldm4(sQh + off, qh[kk][0], qh[kk][1], qh[kk][2], qh[kk][3]);
            ldm4(sQl + off, ql[kk][0], ql[kk][1], ql[kk][2], ql[kk][3]);
        }
    }

    float oacc[8][4];
    #pragma unroll
    for (int nf = 0; nf < 8; nf++)
        #pragma unroll
        for (int q = 0; q < 4; q++) oacc[nf][q] = 0.0f;
    float m0 = -1e30f, m1 = -1e30f, l0 = 0.0f, l1 = 0.0f;

    for (int sj = 0; sj <= ti; sj++) {
        int s0 = sj * 64;
        __syncthreads();
        copy6464(Kh, Khg + (size_t)s0 * ld);
        copy6464(Kl, Khg + (size_t)s0 * ld + 3 * TD);
        copy6464(Vh, Vhg + (size_t)s0 * ld);
        copy6464(Vl, Vhg + (size_t)s0 * ld + 3 * TD);
        __syncthreads();

        // ---- S = Q K^T (3 split terms) ----
        float sacc[8][4];
        #pragma unroll
        for (int nf = 0; nf < 8; nf++)
            #pragma unroll
            for (int q = 0; q < 4; q++) sacc[nf][q] = 0.0f;
        #pragma unroll
        for (int kk = 0; kk < 4; kk++) {
            uint32_t bh4[4][4], bl4[4][4];
            int row = (lane & 7) + (((lane >> 4) & 1) << 3);
            uint32_t coff = kk * 32 + (((lane >> 3) & 1) << 4);
            #pragma unroll
            for (int g = 0; g < 4; g++) {
                uint32_t off = (g * 16 + row) * (FROW * 2) + coff;
                ldm4(sKh + off, bh4[g][0], bh4[g][1], bh4[g][2], bh4[g][3]);
                ldm4(sKl + off, bl4[g][0], bl4[g][1], bl4[g][2], bl4[g][3]);
            }
            #pragma unroll
            for (int nf = 0; nf < 8; nf++) {
                uint32_t b0 = bh4[nf >> 1][(nf & 1) * 2];
                uint32_t b1 = bh4[nf >> 1][(nf & 1) * 2 + 1];
                mma16816(sacc[nf], qh[kk], b0, b1);
                mma16816(sacc[nf], ql[kk], b0, b1);
                mma16816(sacc[nf], qh[kk],
                         bl4[nf >> 1][(nf & 1) * 2],
                         bl4[nf >> 1][(nf & 1) * 2 + 1]);
            }
        }

        // ---- scale + causal mask ----
        bool diag = (sj == ti);
        int rloc0 = wid * 16 + (lane >> 2);
        #pragma unroll
        for (int nf = 0; nf < 8; nf++) {
            #pragma unroll
            for (int q = 0; q < 4; q++) {
                float v = sacc[nf][q] * 0.125f;
                if (diag) {
                    int col = nf * 8 + (lane & 3) * 2 + (q & 1);
                    int rr = rloc0 + (q >> 1) * 8;
                    if (col > rr) v = -1e30f;
                }
                sacc[nf][q] = v;
            }
        }

        // ---- online softmax (quad-lane reduction) ----
        float mx0 = -1e30f, mx1 = -1e30f;
        #pragma unroll
        for (int nf = 0; nf < 8; nf++) {
            mx0 = fmaxf(mx0, fmaxf(sacc[nf][0], sacc[nf][1]));
            mx1 = fmaxf(mx1, fmaxf(sacc[nf][2], sacc[nf][3]));
        }
        #pragma unroll
        for (int o = 1; o <= 2; o <<= 1) {
            mx0 = fmaxf(mx0, __shfl_xor_sync(0xffffffffu, mx0, o));
            mx1 = fmaxf(mx1, __shfl_xor_sync(0xffffffffu, mx1, o));
        }
        float mn0 = fmaxf(m0, mx0), mn1 = fmaxf(m1, mx1);
        float sc0 = __expf(m0 - mn0), sc1 = __expf(m1 - mn1);
        float rs0 = 0.0f, rs1 = 0.0f;
        #pragma unroll
        for (int nf = 0; nf < 8; nf++) {
            sacc[nf][0] = __expf(sacc[nf][0] - mn0);
            sacc[nf][1] = __expf(sacc[nf][1] - mn0);
            sacc[nf][2] = __expf(sacc[nf][2] - mn1);
            sacc[nf][3] = __expf(sacc[nf][3] - mn1);
            rs0 += sacc[nf][0] + sacc[nf][1];
            rs1 += sacc[nf][2] + sacc[nf][3];
        }
        #pragma unroll
        for (int o = 1; o <= 2; o <<= 1) {
            rs0 += __shfl_xor_sync(0xffffffffu, rs0, o);
            rs1 += __shfl_xor_sync(0xffffffffu, rs1, o);
        }
        l0 = l0 * sc0 + rs0; l1 = l1 * sc1 + rs1;
        m0 = mn0; m1 = mn1;
        #pragma unroll
        for (int nf = 0; nf < 8; nf++) {
            oacc[nf][0] *= sc0; oacc[nf][1] *= sc0;
            oacc[nf][2] *= sc1; oacc[nf][3] *= sc1;
        }

        // ---- O += P @ V (P repacked in registers, 3 split terms) ----
        #pragma unroll
        for (int kk = 0; kk < 4; kk++) {
            float* p0 = sacc[2 * kk];
            float* p1 = sacc[2 * kk + 1];
            uint32_t aPh[4], aPl[4];
            {
                __nv_bfloat16 hh, llv;
                float r00, r01, r10, r11;
                bf16split(p0[0], hh, llv); r00 = __bfloat162float(llv);
                bf16split(p0[1], hh, llv); r01 = __bfloat162float(llv);
                aPh[0] = packbf2(p0[0], p0[1]); aPl[0] = packbf2(r00, r01);
                bf16split(p0[2], hh, llv); r10 = __bfloat162float(llv);
                bf16split(p0[3], hh, llv); r11 = __bfloat162float(llv);
                aPh[1] = packbf2(p0[2], p0[3]); aPl[1] = packbf2(r10, r11);
                bf16split(p1[0], hh, llv); r00 = __bfloat162float(llv);
                bf16split(p1[1], hh, llv); r01 = __bfloat162float(llv);
                aPh[2] = packbf2(p1[0], p1[1]); aPl[2] = packbf2(r00, r01);
                bf16split(p1[2], hh, llv); r10 = __bfloat162float(llv);
                bf16split(p1[3], hh, llv); r11 = __bfloat162float(llv);
                aPh[3] = packbf2(p1[2], p1[3]); aPl[3] = packbf2(r10, r11);
            }
            uint32_t vh4[4][4], vl4[4][4];
            int srow = kk * 16 + (lane & 15);
            #pragma unroll
            for (int g = 0; g < 4; g++) {
                uint32_t off = srow * (FROW * 2) +
                               (g * 16 + ((lane >> 4) << 3)) * 2;
                ldm4t(sVh + off, vh4[g][0], vh4[g][1], vh4[g][2], vh4[g][3]);
                ldm4t(sVl + off, vl4[g][0], vl4[g][1], vl4[g][2], vl4[g][3]);
            }
            #pragma unroll
            for (int nf = 0; nf < 8; nf++) {
                uint32_t b0 = vh4[nf >> 1][(nf & 1) * 2];
                uint32_t b1 = vh4[nf >> 1][(nf & 1) * 2 + 1];
                mma16816(oacc[nf], aPh, b0, b1);
                mma16816(oacc[nf], aPl, b0, b1);
                mma16816(oacc[nf], aPh,
                         vl4[nf >> 1][(nf & 1) * 2],
                         vl4[nf >> 1][(nf & 1) * 2 + 1]);
            }
        }
    }

    // ---- finalize + split-bf16 store ----
    float inv0 = 1.0f / l0, inv1 = 1.0f / l1;
    int r0 = t0 + wid * 16 + (lane >> 2);
    #pragma unroll
    for (int nf = 0; nf < 8; nf++) {
        int d = nf * 8 + (lane & 3) * 2;
        __nv_bfloat16* base0 =
            oA + (size_t)(b * TT + r0) * (2 * TD) + h * THD + d;
        __nv_bfloat16* base1 =
            oA + (size_t)(b * TT + r0 + 8) * (2 * TD) + h * THD + d;
        __nv_bfloat16 h0, lo0, h1, lo1;
        bf16split(oacc[nf][0] * inv0, h0, lo0);
        bf16split(oacc[nf][1] * inv0, h1, lo1);
        *(__nv_bfloat162*)base0 = __halves2bfloat162(h0, h1);
        *(__nv_bfloat162*)(base0 + TD) = __halves2bfloat162(lo0, lo1);
        bf16split(oacc[nf][2] * inv1, h0, lo0);
        bf16split(oacc[nf][3] * inv1, h1, lo1);
        *(__nv_bfloat162*)base1 = __halves2bfloat162(h0, h1);
        *(__nv_bfloat162*)(base1 + TD) = __halves2bfloat162(lo0, lo1);
    }
}

// ------------------------- launch ------------------------------------------
extern "C" void kernel_launch(void* const* d_in, const int* in_sizes, int n_in,
                              void* d_out, int out_size) {
    const float* x   = (const float*)d_in[0];
    const float* Wq  = (const float*)d_in[1];
    const float* Wk  = (const float*)d_in[2];
    const float* Wv  = (const float*)d_in[3];
    const float* Wo  = (const float*)d_in[4];
    const float* bo  = (const float*)d_in[5];
    const float* W1  = (const float*)d_in[6];
    const float* b1  = (const float*)d_in[7];
    const float* W2  = (const float*)d_in[8];
    const float* b2  = (const float*)d_in[9];
    const float* g1  = (const float*)d_in[10];
    const float* be1 = (const float*)d_in[11];
    const float* g2  = (const float*)d_in[12];
    const float* be2 = (const float*)d_in[13];
    float* out = (float*)d_out;

    __nv_bfloat16 *hA, *qkvb, *oA, *ffA, *wqkv, *wo, *w1, *w2;
    float *x2;
    cudaGetSymbolAddress((void**)&hA,   g_hA);
    cudaGetSymbolAddress((void**)&qkvb, g_qkvb);
    cudaGetSymbolAddress((void**)&oA,   g_oA);
    cudaGetSymbolAddress((void**)&x2,   g_x2);
    cudaGetSymbolAddress((void**)&ffA,  g_ffA);
    cudaGetSymbolAddress((void**)&wqkv, g_wqkv);
    cudaGetSymbolAddress((void**)&wo,   g_wo);
    cudaGetSymbolAddress((void**)&w1,   g_w1);
    cudaGetSymbolAddress((void**)&w2,   g_w2);

    static int attr_set = 0;
    if (!attr_set) {
        cudaFuncSetAttribute(flashT_kernel,
                             cudaFuncAttributeMaxDynamicSharedMemorySize, FB_SMEM);
        cudaFuncSetAttribute(mgemm_kernel<0>,
                             cudaFuncAttributeMaxDynamicSharedMemorySize, MDYN);
        cudaFuncSetAttribute(mgemm_kernel<1>,
                             cudaFuncAttributeMaxDynamicSharedMemorySize, MDYN);
        cudaFuncSetAttribute(mgemm_kernel<2>,
                             cudaFuncAttributeMaxDynamicSharedMemorySize, MDYN);
        cudaFuncSetAttribute(mgemm_kernel<3>,
                             cudaFuncAttributeMaxDynamicSharedMemorySize, MDYN);
        attr_set = 1;
    }

    dim3 cb(32, 8);
    qkvconv_kernel<<<dim3(2, 32, 48), cb>>>(Wq, Wk, Wv, wqkv);
    wconv_kernel<<<dim3(32, 32), cb>>>(Wo, TD, wo, 2 * TD, TD);
    wconv_kernel<<<dim3(128, 32), cb>>>(W1, TDFF, w1, 2 * TD, TD);
    wconv_kernel<<<dim3(32, 128), cb>>>(W2, TD, w2, 2 * TDFF, TDFF);

    // LN1 -> split operand
    ln_kernel<<<BT, 256>>>(x, g1, be1, hA);
    // QKV GEMM -> split bf16 output (attention operands)
    mgemm_kernel<3><<<dim3(24, 32), 256, MDYN>>>(
        hA, wqkv, nullptr, qkvb, TD, 2 * TD, 2 * TD, 6 * TD, 3 * TD,
        nullptr, nullptr, 0);
    // HMMA flash attention -> split operand
    flashT_kernel<<<dim3(32, TB * TH), 128, FB_SMEM>>>(qkvb, oA);
    // x2 = x + o @ Wo + bo
    mgemm_kernel<1><<<dim3(8, 32), 256, MDYN>>>(
        oA, wo, x2, nullptr, TD, 2 * TD, 2 * TD, TD, 0, bo, x, TD);
    // LN2 -> split operand
    ln_kernel<<<BT, 256>>>(x2, g2, be2, hA);
    // ff = gelu(h2 @ W1 + b1) -> split operand
    mgemm_kernel<2><<<dim3(32, 32), 256, MDYN>>>(
        hA, w1, nullptr, ffA, TD, 2 * TD, 2 * TD, 2 * TDFF, TDFF,
        b1, nullptr, 0);
    // out = x2 + ff @ W2 + b2
    mgemm_kernel<1><<<dim3(8, 32), 256, MDYN>>>(
        ffA, w2, out, nullptr, TDFF, 2 * TDFF, 2 * TDFF, TD, 0, b2, x2, TD);
}